// round 10
// baseline (speedup 1.0000x reference)
#include <cuda_runtime.h>
#include <stdint.h>

// RescaleProbMask: x (32, 256, 256, 16) fp32.
//   p[h,w] = mean over (batch, channel); out = scale(p)*x + bias(p).
//
// Single-wave persistent grid (1184 CTAs = 148 SMs x occ 8), grid-stride
// over 8192 tiles. Per-tile mapping identical to the 44.0us best:
//   8 pixels/tile; warp w covers batches 4w..4w+3 with one coalesced
//   512B LDG.128 run per batch (4 loads/thread, payload 16 regs).
//   Reduce: lane sum -> shfl_xor(1),(2) -> 8x8 smem (parity-buffered,
//   ONE __syncthreads per tile) -> per-pixel (scale,bias) -> FMA -> STG.
// Rationale: removes 6 wave transitions + the 0.92-fill tail wave and the
// per-CTA load-drain bubble at every wave boundary; unlike R7 the loop is
// kept minimal to preserve the 32-reg / occ-8 envelope (no dup payload).

#define NB    32
#define NHW   (256 * 256)
#define NC    16
#define ALPHA 0.25f

#define PIX_PER_CTA 8
#define F4_PER_TILE (PIX_PER_CTA * NC / 4)   // 32 float4 per batch per tile
#define PLANE_F4    ((NHW * NC) / 4)         // 262144 float4 per batch plane
#define NTILES      (NHW / PIX_PER_CTA)      // 8192
#define GRID        1184                      // 148 SMs x 8 CTAs, single wave

__global__ __launch_bounds__(256, 8)
void rescale_prob_mask_kernel(const float* __restrict__ x,
                              float* __restrict__ out) {
    __shared__ float psum[2][PIX_PER_CTA][8];   // parity-buffered [pixel][warp]

    const int tid  = threadIdx.x;
    const int warp = tid >> 5;
    const int lane = tid & 31;
    const int pix  = lane >> 2;

    const float4* __restrict__ xp = reinterpret_cast<const float4*>(x);
    float4*       __restrict__ op = reinterpret_cast<float4*>(out);

    // float4 index of batch (warp*4) for the first tile of this CTA
    size_t idx = (size_t)blockIdx.x * F4_PER_TILE + lane
               + (size_t)(warp * 4) * PLANE_F4;
    const size_t step = (size_t)GRID * F4_PER_TILE;

    int buf = 0;
    for (int tile = blockIdx.x; tile < NTILES; tile += GRID) {
        // 4 front-batched coalesced streaming loads
        float4 v0 = __ldcs(xp + idx);
        float4 v1 = __ldcs(xp + idx +     PLANE_F4);
        float4 v2 = __ldcs(xp + idx + 2 * PLANE_F4);
        float4 v3 = __ldcs(xp + idx + 3 * PLANE_F4);

        // lane-local partial sum (4 batches x 4 channels of pixel `pix`)
        float s = ((v0.x + v0.y) + (v0.z + v0.w))
                + ((v1.x + v1.y) + (v1.z + v1.w))
                + ((v2.x + v2.y) + (v2.z + v2.w))
                + ((v3.x + v3.y) + (v3.z + v3.w));

        // reduce over the 4 lanes sharing a pixel (all 16 channels)
        s += __shfl_xor_sync(0xffffffffu, s, 1);
        s += __shfl_xor_sync(0xffffffffu, s, 2);

        if ((lane & 3) == 0)
            psum[buf][pix][warp] = s;
        __syncthreads();      // one barrier/tile; parity buffer makes it safe

        const float tot = psum[buf][pix][0] + psum[buf][pix][1]
                        + psum[buf][pix][2] + psum[buf][pix][3]
                        + psum[buf][pix][4] + psum[buf][pix][5]
                        + psum[buf][pix][6] + psum[buf][pix][7];

        const float p = tot * (1.0f / (NB * NC));

        float scale, bias;
        if (p >= ALPHA) {
            scale = ALPHA / p;
            bias  = 0.0f;
        } else {
            const float beta = (1.0f - ALPHA) / (1.0f - p);
            scale = beta;
            bias  = 1.0f - beta;
        }

        v0.x = fmaf(scale, v0.x, bias); v0.y = fmaf(scale, v0.y, bias);
        v0.z = fmaf(scale, v0.z, bias); v0.w = fmaf(scale, v0.w, bias);
        v1.x = fmaf(scale, v1.x, bias); v1.y = fmaf(scale, v1.y, bias);
        v1.z = fmaf(scale, v1.z, bias); v1.w = fmaf(scale, v1.w, bias);
        v2.x = fmaf(scale, v2.x, bias); v2.y = fmaf(scale, v2.y, bias);
        v2.z = fmaf(scale, v2.z, bias); v2.w = fmaf(scale, v2.w, bias);
        v3.x = fmaf(scale, v3.x, bias); v3.y = fmaf(scale, v3.y, bias);
        v3.z = fmaf(scale, v3.z, bias); v3.w = fmaf(scale, v3.w, bias);

        __stcs(op + idx,                v0);
        __stcs(op + idx +     PLANE_F4, v1);
        __stcs(op + idx + 2 * PLANE_F4, v2);
        __stcs(op + idx + 3 * PLANE_F4, v3);

        idx += step;
        buf ^= 1;
    }
}

extern "C" void kernel_launch(void* const* d_in, const int* in_sizes, int n_in,
                              void* d_out, int out_size) {
    const float* x   = (const float*)d_in[0];
    float*       out = (float*)d_out;

    rescale_prob_mask_kernel<<<GRID, 256>>>(x, out);
}

// round 11
// speedup vs baseline: 1.1316x; 1.1316x over previous
#include <cuda_runtime.h>
#include <stdint.h>

// RescaleProbMask: x (32, 256, 256, 16) fp32.
//   p[h,w] = mean over (batch, channel); out = scale(p)*x + bias(p).
//
// R6 structure (best: 44.0us, occ 88%, DRAM 74%) with the last untested
// memory-path mechanism: WRITE-THROUGH stores (st.global.wt) so the
// 134MB/iter out-stream does not allocate dirty L2 lines, plus
// L2::evict_last on all x reads. Hypothesis: store-allocation churn is
// what pins x's cross-replay L2 hit rate at ~41%; removing allocation
// lets x (134MB vs 126MB L2) reach high residency.
//
// Mapping (unchanged): 8 pixels/CTA; warp w covers batches 4w..4w+3;
// lanes 0-15 = batch half 0, 16-31 = half 1; two 32B (v4.b64) accesses
// per lane. Reduce: lane sum -> shfl_xor(1) -> shfl_xor(16) -> 8x8 smem
// -> per-pixel (scale,bias) -> FMA -> stores.

#define NB    32
#define NHW   (256 * 256)
#define NC    16
#define ALPHA 0.25f

#define PIX_PER_CTA 8
#define PLANE ((size_t)NHW * NC)       // floats per batch plane = 1048576

__device__ __forceinline__ void ld_x32(const float* p, float* v) {
    uint64_t q0, q1, q2, q3;
    asm("ld.global.nc.L2::evict_last.v4.b64 {%0,%1,%2,%3}, [%4];"
        : "=l"(q0), "=l"(q1), "=l"(q2), "=l"(q3) : "l"(p));
    asm("mov.b64 {%0,%1}, %2;" : "=f"(v[0]), "=f"(v[1]) : "l"(q0));
    asm("mov.b64 {%0,%1}, %2;" : "=f"(v[2]), "=f"(v[3]) : "l"(q1));
    asm("mov.b64 {%0,%1}, %2;" : "=f"(v[4]), "=f"(v[5]) : "l"(q2));
    asm("mov.b64 {%0,%1}, %2;" : "=f"(v[6]), "=f"(v[7]) : "l"(q3));
}

__device__ __forceinline__ void st_out32_wt(float* p, const float* v) {
    uint64_t q0, q1, q2, q3;
    asm("mov.b64 %0, {%1,%2};" : "=l"(q0) : "f"(v[0]), "f"(v[1]));
    asm("mov.b64 %0, {%1,%2};" : "=l"(q1) : "f"(v[2]), "f"(v[3]));
    asm("mov.b64 %0, {%1,%2};" : "=l"(q2) : "f"(v[4]), "f"(v[5]));
    asm("mov.b64 %0, {%1,%2};" : "=l"(q3) : "f"(v[6]), "f"(v[7]));
    asm volatile("st.global.wt.v4.b64 [%0], {%1,%2,%3,%4};"
                 :: "l"(p), "l"(q0), "l"(q1), "l"(q2), "l"(q3) : "memory");
}

__global__ __launch_bounds__(256, 8)
void rescale_prob_mask_kernel(const float* __restrict__ x,
                              float* __restrict__ out) {
    __shared__ float psum[PIX_PER_CTA][8];   // [pixel][warp]

    const int tid  = threadIdx.x;
    const int warp = tid >> 5;
    const int lane = tid & 31;
    const int li   = lane & 15;              // position within half-warp
    const int half = lane >> 4;              // batch half (0/1)
    const int pix  = li >> 1;                // pixel within CTA (0..7)

    const size_t off = (size_t)blockIdx.x * (PIX_PER_CTA * NC) + (size_t)li * 8;

    const int b0 = warp * 4 + half;          // first batch for this lane
    const int b1 = b0 + 2;                   // second batch

    const size_t i0 = (size_t)b0 * PLANE + off;
    const size_t i1 = (size_t)b1 * PLANE + off;

    float a[8], b[8];
    ld_x32(x + i0, a);
    ld_x32(x + i1, b);

    // lane-local partial sum (2 batches x 8 channels of pixel `pix`)
    float s = ((a[0] + a[1]) + (a[2] + a[3])) + ((a[4] + a[5]) + (a[6] + a[7]))
            + ((b[0] + b[1]) + (b[2] + b[3])) + ((b[4] + b[5]) + (b[6] + b[7]));

    // xor1: other 8 channels of the pixel; xor16: other batch pair
    s += __shfl_xor_sync(0xffffffffu, s, 1);
    s += __shfl_xor_sync(0xffffffffu, s, 16);

    if (lane < 16 && (li & 1) == 0)
        psum[pix][warp] = s;
    __syncthreads();

    float tot = psum[pix][0] + psum[pix][1] + psum[pix][2] + psum[pix][3]
              + psum[pix][4] + psum[pix][5] + psum[pix][6] + psum[pix][7];

    const float p = tot * (1.0f / (NB * NC));

    float scale, bias;
    if (p >= ALPHA) {
        scale = ALPHA / p;
        bias  = 0.0f;
    } else {
        const float beta = (1.0f - ALPHA) / (1.0f - p);
        scale = beta;
        bias  = 1.0f - beta;
    }

    #pragma unroll
    for (int k = 0; k < 8; k++) {
        a[k] = fmaf(scale, a[k], bias);
        b[k] = fmaf(scale, b[k], bias);
    }

    st_out32_wt(out + i0, a);
    st_out32_wt(out + i1, b);
}

extern "C" void kernel_launch(void* const* d_in, const int* in_sizes, int n_in,
                              void* d_out, int out_size) {
    const float* x   = (const float*)d_in[0];
    float*       out = (float*)d_out;

    const int blocks = NHW / PIX_PER_CTA;   // 8192
    rescale_prob_mask_kernel<<<blocks, 256>>>(x, out);
}